// round 1
// baseline (speedup 1.0000x reference)
#include <cuda_runtime.h>

#define N_NODES 8192
#define F_IN    512
#define F_OUT   64
#define LRELU_ALPHA 0.2f

// Scratch (no cudaMalloc allowed): Wh (2 MB) + attention logit vectors.
__device__ float g_Wh[N_NODES * F_OUT];
__device__ float g_e1[N_NODES];
__device__ float g_e2[N_NODES];

// ---------------------------------------------------------------------------
// Kernel 1: Wh = h @ W, fused e1 = Wh@a1, e2 = Wh@a2.
// One warp per row; lane owns output cols (2*lane, 2*lane+1).
// h row staged in registers, broadcast via shfl; W rows read as float2
// (256B coalesced per warp, W = 128KB -> L1/L2 resident).
// ---------------------------------------------------------------------------
__global__ void __launch_bounds__(256) wh_kernel(const float* __restrict__ h,
                                                 const float* __restrict__ W,
                                                 const float* __restrict__ a) {
    const int lane = threadIdx.x & 31;
    const int i = blockIdx.x * 8 + (threadIdx.x >> 5);
    if (i >= N_NODES) return;

    const float* hrow = h + (size_t)i * F_IN;
    float hreg[F_IN / 32];
#pragma unroll
    for (int t = 0; t < F_IN / 32; ++t) hreg[t] = hrow[t * 32 + lane];

    float accx = 0.f, accy = 0.f;
    const float2* W2 = (const float2*)W;
    for (int t = 0; t < F_IN / 32; ++t) {
#pragma unroll
        for (int s = 0; s < 32; ++s) {
            float hv = __shfl_sync(0xffffffffu, hreg[t], s);
            float2 w = W2[(size_t)(t * 32 + s) * (F_OUT / 2) + lane];
            accx = fmaf(hv, w.x, accx);
            accy = fmaf(hv, w.y, accy);
        }
    }

    g_Wh[(size_t)i * F_OUT + 2 * lane]     = accx;
    g_Wh[(size_t)i * F_OUT + 2 * lane + 1] = accy;

    // e1[i] = Wh[i,:] . a[:64],  e2[i] = Wh[i,:] . a[64:128]
    float e1p = accx * a[2 * lane]         + accy * a[2 * lane + 1];
    float e2p = accx * a[F_OUT + 2 * lane] + accy * a[F_OUT + 2 * lane + 1];
#pragma unroll
    for (int off = 16; off; off >>= 1) {
        e1p += __shfl_xor_sync(0xffffffffu, e1p, off);
        e2p += __shfl_xor_sync(0xffffffffu, e2p, off);
    }
    if (lane == 0) { g_e1[i] = e1p; g_e2[i] = e2p; }
}

// ---------------------------------------------------------------------------
// Kernel 2: flash-style masked softmax-aggregate + ELU.
//   p_ij = adj_ij>0 ? exp(leaky_relu(e1_i + e2_j)) : 0        (no max needed)
//   out_i = elu( (sum_j p_ij * Wh_j) / (sum_j p_ij) )
// One warp per row i; lane owns 2 output columns. Per 32-j chunk each lane
// computes p for its own j, then a ballot-compressed loop broadcasts the
// nonzero p's (warp-uniform control flow -> real skipping of ~50% zeros).
// ---------------------------------------------------------------------------
__global__ void __launch_bounds__(256) attn_kernel(const int* __restrict__ adj,
                                                   float* __restrict__ out) {
    __shared__ float s_e2[N_NODES];   // 32 KB
    for (int k = threadIdx.x; k < N_NODES; k += blockDim.x) s_e2[k] = g_e2[k];
    __syncthreads();

    const int lane = threadIdx.x & 31;
    const int i = blockIdx.x * 8 + (threadIdx.x >> 5);

    const float e1i = g_e1[i];
    const int* __restrict__ arow = adj + (size_t)i * N_NODES;
    const float2* __restrict__ Wh2 = (const float2*)g_Wh;

    float accx = 0.f, accy = 0.f, den = 0.f;

    for (int jb = 0; jb < N_NODES; jb += 32) {
        int   av = arow[jb + lane];
        float s  = e1i + s_e2[jb + lane];
        s = (s > 0.f) ? s : LRELU_ALPHA * s;
        float p = (av > 0) ? __expf(s) : 0.f;
        den += p;                                   // per-lane partial of sum_j p
        unsigned m = __ballot_sync(0xffffffffu, p != 0.f);
        while (m) {
            int t = __ffs(m) - 1;
            m &= m - 1;
            float ps = __shfl_sync(0xffffffffu, p, t);
            float2 w = Wh2[(size_t)(jb + t) * (F_OUT / 2) + lane];
            accx = fmaf(ps, w.x, accx);
            accy = fmaf(ps, w.y, accy);
        }
    }

    // reduce denominator across the warp (acc stays per-lane: distinct columns)
#pragma unroll
    for (int off = 16; off; off >>= 1)
        den += __shfl_xor_sync(0xffffffffu, den, off);

    if (den == 0.f) den = 1.f;   // unreachable for random adj; avoids NaN
    float inv = 1.f / den;
    float vx = accx * inv;
    float vy = accy * inv;
    out[(size_t)i * F_OUT + 2 * lane]     = (vx > 0.f) ? vx : expm1f(vx);
    out[(size_t)i * F_OUT + 2 * lane + 1] = (vy > 0.f) ? vy : expm1f(vy);
}

// ---------------------------------------------------------------------------
extern "C" void kernel_launch(void* const* d_in, const int* in_sizes, int n_in,
                              void* d_out, int out_size) {
    const float* h   = (const float*)d_in[0];   // [8192, 512]
    const float* W   = (const float*)d_in[1];   // [512, 64]
    const float* a   = (const float*)d_in[2];   // [128, 1]
    const int*   adj = (const int*)d_in[3];     // [8192, 8192]
    float* out = (float*)d_out;                 // [8192, 64]

    wh_kernel<<<N_NODES / 8, 256>>>(h, W, a);
    attn_kernel<<<N_NODES / 8, 256>>>(adj, out);
}

// round 3
// speedup vs baseline: 6.3692x; 6.3692x over previous
#include <cuda_runtime.h>
#include <cuda_bf16.h>
#include <cstdint>

#define NN      8192
#define F_IN    512
#define NOUT    64
#define LRA     0.2f
#define JSPLITS 4
#define JLEN    (NN / JSPLITS)     // 2048
#define NCH     (JLEN / 16)        // 128 chunks of k=16
#define BST     48                 // padded bytes per n-row in staged B

// ---------------- device scratch (no cudaMalloc allowed) -------------------
__device__ __align__(16) __nv_bfloat16 g_WhT_hi[NOUT * NN];  // [n][k] K-major
__device__ __align__(16) __nv_bfloat16 g_WhT_lo[NOUT * NN];
__device__ float g_e1[NN];
__device__ float g_e2[NN];
__device__ float g_pacc[JSPLITS][NN][NOUT];
__device__ float g_pden[JSPLITS][NN];

// ---------------- helpers ---------------------------------------------------
__device__ __forceinline__ void mma16816(float* d, const unsigned* a, const unsigned* b) {
    asm volatile(
        "mma.sync.aligned.m16n8k16.row.col.f32.bf16.bf16.f32 "
        "{%0,%1,%2,%3}, {%4,%5,%6,%7}, {%8,%9}, {%0,%1,%2,%3};"
        : "+f"(d[0]), "+f"(d[1]), "+f"(d[2]), "+f"(d[3])
        : "r"(a[0]), "r"(a[1]), "r"(a[2]), "r"(a[3]), "r"(b[0]), "r"(b[1]));
}
__device__ __forceinline__ void ldsm4(unsigned* r, uint32_t addr) {
    asm volatile("ldmatrix.sync.aligned.m8n8.x4.shared.b16 {%0,%1,%2,%3}, [%4];"
                 : "=r"(r[0]), "=r"(r[1]), "=r"(r[2]), "=r"(r[3]) : "r"(addr));
}
// pack: low half = pe (even col), high half = po (odd col)
__device__ __forceinline__ unsigned cvt2(float po, float pe) {
    unsigned r;
    asm("cvt.rn.bf16x2.f32 %0, %1, %2;" : "=r"(r) : "f"(po), "f"(pe));
    return r;
}
__device__ __forceinline__ float bfhf(float x) {
    return __bfloat162float(__float2bfloat16_rn(x));
}

// ---------------------------------------------------------------------------
// Kernel 1: Wh = h @ W (warp per row, smem h-broadcast); emits K-major bf16
// hi/lo WhT + e1/e2.
// ---------------------------------------------------------------------------
__global__ void __launch_bounds__(256) wh_kernel(const float* __restrict__ h,
                                                 const float* __restrict__ W,
                                                 const float* __restrict__ a) {
    __shared__ float s_h[8][F_IN];
    const int l = threadIdx.x & 31;
    const int w = threadIdx.x >> 5;
    const int i = blockIdx.x * 8 + w;

    const float* hrow = h + (size_t)i * F_IN;
    for (int t = l; t < F_IN; t += 32) s_h[w][t] = hrow[t];
    __syncwarp();

    float ax = 0.f, ay = 0.f;
    const float2* W2 = (const float2*)W;
#pragma unroll 8
    for (int k = 0; k < F_IN; ++k) {
        float hv = s_h[w][k];
        float2 wv = W2[k * 32 + l];
        ax = fmaf(hv, wv.x, ax);
        ay = fmaf(hv, wv.y, ay);
    }

    __nv_bfloat16 hx = __float2bfloat16_rn(ax);
    __nv_bfloat16 hy = __float2bfloat16_rn(ay);
    g_WhT_hi[(size_t)(2 * l)     * NN + i] = hx;
    g_WhT_hi[(size_t)(2 * l + 1) * NN + i] = hy;
    g_WhT_lo[(size_t)(2 * l)     * NN + i] = __float2bfloat16_rn(ax - __bfloat162float(hx));
    g_WhT_lo[(size_t)(2 * l + 1) * NN + i] = __float2bfloat16_rn(ay - __bfloat162float(hy));

    float e1p = ax * a[2 * l]        + ay * a[2 * l + 1];
    float e2p = ax * a[NOUT + 2 * l] + ay * a[NOUT + 2 * l + 1];
#pragma unroll
    for (int off = 16; off; off >>= 1) {
        e1p += __shfl_xor_sync(0xffffffffu, e1p, off);
        e2p += __shfl_xor_sync(0xffffffffu, e2p, off);
    }
    if (l == 0) { g_e1[i] = e1p; g_e2[i] = e2p; }
}

// ---------------------------------------------------------------------------
// Kernel 2: fused masked-exp + bf16 split GEMM via mma.sync m16n8k16.
// Grid 128 = 32 row-tiles(256 rows) x 4 j-splits. 256 threads / 8 warps.
// Warp w owns rows [w*32, w*32+32) x all 64 cols:
//   2 m-tiles x 8 n-tiles of m16n8 accumulators (64 fp32 regs/lane).
// P fragments generated in-register (exp per fragment slot); WhT staged in
// smem + ldmatrix; adj & B register-prefetched one chunk ahead.
// ---------------------------------------------------------------------------
__global__ void __launch_bounds__(256, 1) attn_kernel(const int* __restrict__ adj) {
    __shared__ float s_e2[JLEN];                      // 8 KB
    __shared__ __align__(16) char s_B[2][64 * BST];   // hi,lo staged B (6 KB)

    const int tid = threadIdx.x;
    const int w = tid >> 5;
    const int l = tid & 31;
    const int i0 = (blockIdx.x >> 2) * 256;
    const int split = blockIdx.x & 3;
    const int j0 = split * JLEN;

    for (int k = tid; k < JLEN; k += 256) s_e2[k] = g_e2[j0 + k];

    const int rq = l >> 2;            // 0..7
    const int cq = (l & 3) * 2;       // 0,2,4,6

    // this lane's 4 rows (offsets 0,8,16,24 within the warp's 32-row slab)
    float e1r[4];
    const int* rbase[4];
#pragma unroll
    for (int k = 0; k < 4; ++k) {
        int row = i0 + w * 32 + 8 * k + rq;
        e1r[k] = g_e1[row];
        rbase[k] = adj + (size_t)row * NN + j0 + cq;
    }

    // B stage assignment: 128 threads hi, 128 lo; each stores one uint4/chunk
    const int hl = tid >> 7;
    const int sn = (tid & 127) >> 1;
    const int skh = tid & 1;
    const __nv_bfloat16* srcp =
        (hl ? g_WhT_lo : g_WhT_hi) + (size_t)sn * NN + j0 + skh * 8;
    char* dstp = &s_B[hl][sn * BST + skh * 16];

    // ldmatrix per-lane address offset
    const int g = l >> 3, lr = l & 7;
    const uint32_t lane_off = (uint32_t)((lr + ((g >> 1) << 3)) * BST + ((g & 1) << 4));
    const uint32_t sB_hi = (uint32_t)__cvta_generic_to_shared(&s_B[0][0]) + lane_off;
    const uint32_t sB_lo = (uint32_t)__cvta_generic_to_shared(&s_B[1][0]) + lane_off;

    float acc[2][8][4];
#pragma unroll
    for (int t = 0; t < 2; ++t)
#pragma unroll
        for (int n = 0; n < 8; ++n)
#pragma unroll
            for (int q = 0; q < 4; ++q) acc[t][n][q] = 0.f;
    float den4[4] = {0.f, 0.f, 0.f, 0.f};

    // prefetch chunk 0
    uint4 breg = *(const uint4*)srcp;
    int2 alo[4], ahi[4];
#pragma unroll
    for (int k = 0; k < 4; ++k) {
        alo[k] = *(const int2*)(rbase[k]);
        ahi[k] = *(const int2*)(rbase[k] + 8);
    }
    __syncthreads();   // e2 staged

    for (int c = 0; c < NCH; ++c) {
        // ---- generate A fragments (P hi/lo) for chunk c ----
        const float* e2p = s_e2 + c * 16;
        float2 e2a = *(const float2*)(e2p + cq);
        float2 e2b = *(const float2*)(e2p + cq + 8);
        unsigned Ah[2][4], Al[2][4];
#pragma unroll
        for (int k = 0; k < 4; ++k) {
            const int t = k >> 1, rp = k & 1;
            const float e1v = e1r[k];
            float s0 = e1v + e2a.x; s0 = s0 > 0.f ? s0 : LRA * s0;
            float s1 = e1v + e2a.y; s1 = s1 > 0.f ? s1 : LRA * s1;
            float s2 = e1v + e2b.x; s2 = s2 > 0.f ? s2 : LRA * s2;
            float s3 = e1v + e2b.y; s3 = s3 > 0.f ? s3 : LRA * s3;
            float p0 = alo[k].x > 0 ? __expf(s0) : 0.f;
            float p1 = alo[k].y > 0 ? __expf(s1) : 0.f;
            float p2 = ahi[k].x > 0 ? __expf(s2) : 0.f;
            float p3 = ahi[k].y > 0 ? __expf(s3) : 0.f;
            den4[k] += (p0 + p1) + (p2 + p3);
            float h0 = bfhf(p0), h1 = bfhf(p1), h2 = bfhf(p2), h3 = bfhf(p3);
            Ah[t][rp]     = cvt2(h1, h0);
            Ah[t][rp + 2] = cvt2(h3, h2);
            Al[t][rp]     = cvt2(p1 - h1, p0 - h0);
            Al[t][rp + 2] = cvt2(p3 - h3, p2 - h2);
        }

        // ---- prefetch next chunk's adj into regs ----
        if (c + 1 < NCH) {
#pragma unroll
            for (int k = 0; k < 4; ++k) {
                alo[k] = *(const int2*)(rbase[k] + (c + 1) * 16);
                ahi[k] = *(const int2*)(rbase[k] + (c + 1) * 16 + 8);
            }
        }

        // ---- stage B(c) into smem ----
        __syncthreads();                       // prior ldmatrix done everywhere
        *(uint4*)dstp = breg;
        __syncthreads();                       // stage visible

        // ---- B hi fragments + prefetch next B ----
        unsigned Bh[8][2];
#pragma unroll
        for (int np = 0; np < 4; ++np) ldsm4(&Bh[2 * np][0], sB_hi + np * (16 * BST));
        if (c + 1 < NCH) breg = *(const uint4*)(srcp + (c + 1) * 16);

        // ---- products using Bh: Ah*Bh and Al*Bh ----
#pragma unroll
        for (int t = 0; t < 2; ++t)
#pragma unroll
            for (int n = 0; n < 8; ++n) mma16816(acc[t][n], Ah[t], Bh[n]);
#pragma unroll
        for (int t = 0; t < 2; ++t)
#pragma unroll
            for (int n = 0; n < 8; ++n) mma16816(acc[t][n], Al[t], Bh[n]);

        // ---- B lo fragments, product Ah*Bl ----
        unsigned Bl[8][2];
#pragma unroll
        for (int np = 0; np < 4; ++np) ldsm4(&Bl[2 * np][0], sB_lo + np * (16 * BST));
#pragma unroll
        for (int t = 0; t < 2; ++t)
#pragma unroll
            for (int n = 0; n < 8; ++n) mma16816(acc[t][n], Ah[t], Bl[n]);
    }

    // ---- denominators: reduce over the 4-lane quad covering each row ----
#pragma unroll
    for (int k = 0; k < 4; ++k) {
        den4[k] += __shfl_xor_sync(0xffffffffu, den4[k], 1);
        den4[k] += __shfl_xor_sync(0xffffffffu, den4[k], 2);
    }
    if ((l & 3) == 0) {
#pragma unroll
        for (int k = 0; k < 4; ++k)
            g_pden[split][i0 + w * 32 + 8 * k + rq] = den4[k];
    }

    // ---- write fp32 partial numerators ----
#pragma unroll
    for (int t = 0; t < 2; ++t) {
        const int row = i0 + w * 32 + t * 16 + rq;
#pragma unroll
        for (int n = 0; n < 8; ++n) {
            float2 v01 = make_float2(acc[t][n][0], acc[t][n][1]);
            float2 v23 = make_float2(acc[t][n][2], acc[t][n][3]);
            *(float2*)&g_pacc[split][row][n * 8 + cq]     = v01;
            *(float2*)&g_pacc[split][row + 8][n * 8 + cq] = v23;
        }
    }
}

// ---------------------------------------------------------------------------
// Kernel 3: combine splits, normalize, ELU.
// ---------------------------------------------------------------------------
__global__ void __launch_bounds__(256) combine_kernel(float* __restrict__ out) {
    const int idx = blockIdx.x * 256 + threadIdx.x;   // over 8192*64
    const int i = idx >> 6;
    const int c = idx & 63;
    float acc = g_pacc[0][i][c] + g_pacc[1][i][c] + g_pacc[2][i][c] + g_pacc[3][i][c];
    float den = g_pden[0][i] + g_pden[1][i] + g_pden[2][i] + g_pden[3][i];
    if (den == 0.f) den = 1.f;
    float v = acc / den;
    out[idx] = v > 0.f ? v : expm1f(v);
}

// ---------------------------------------------------------------------------
extern "C" void kernel_launch(void* const* d_in, const int* in_sizes, int n_in,
                              void* d_out, int out_size) {
    const float* h   = (const float*)d_in[0];
    const float* W   = (const float*)d_in[1];
    const float* a   = (const float*)d_in[2];
    const int*   adj = (const int*)d_in[3];
    float* out = (float*)d_out;

    wh_kernel<<<NN / 8, 256>>>(h, W, a);
    attn_kernel<<<(NN / 256) * JSPLITS, 256>>>(adj);
    combine_kernel<<<NN * NOUT / 256, 256>>>(out);
}

// round 4
// speedup vs baseline: 7.1312x; 1.1196x over previous
#include <cuda_runtime.h>
#include <cuda_bf16.h>
#include <cstdint>

#define NN      8192
#define F_IN    512
#define NOUT    64
#define LRA     0.2f
#define JSPLITS 8
#define JLEN    (NN / JSPLITS)     // 1024
#define NCH     (JLEN / 16)        // 64 chunks of k=16
#define NBLK    (NCH / 2)          // 32 blocks of k=32
#define BST     80                 // padded bytes per n-row in staged B
#define BBUF    (64 * BST)         // 5120 B per (stage,hi/lo)

// ---------------- device scratch (no cudaMalloc allowed) -------------------
__device__ __align__(16) __nv_bfloat16 g_WhT_hi[NOUT * NN];  // [n][k] K-major
__device__ __align__(16) __nv_bfloat16 g_WhT_lo[NOUT * NN];
__device__ float g_e1[NN];
__device__ float g_e2[NN];
__device__ float g_pacc[JSPLITS][NN][NOUT];
__device__ float g_pden[JSPLITS][NN];

// ---------------- helpers ---------------------------------------------------
__device__ __forceinline__ void mma16816(float* d, const unsigned* a, const unsigned* b) {
    asm volatile(
        "mma.sync.aligned.m16n8k16.row.col.f32.bf16.bf16.f32 "
        "{%0,%1,%2,%3}, {%4,%5,%6,%7}, {%8,%9}, {%0,%1,%2,%3};"
        : "+f"(d[0]), "+f"(d[1]), "+f"(d[2]), "+f"(d[3])
        : "r"(a[0]), "r"(a[1]), "r"(a[2]), "r"(a[3]), "r"(b[0]), "r"(b[1]));
}
__device__ __forceinline__ void ldsm4(unsigned* r, uint32_t addr) {
    asm volatile("ldmatrix.sync.aligned.m8n8.x4.shared.b16 {%0,%1,%2,%3}, [%4];"
                 : "=r"(r[0]), "=r"(r[1]), "=r"(r[2]), "=r"(r[3]) : "r"(addr));
}
__device__ __forceinline__ unsigned cvt2(float po, float pe) {   // hi=po, lo=pe
    unsigned r;
    asm("cvt.rn.bf16x2.f32 %0, %1, %2;" : "=r"(r) : "f"(po), "f"(pe));
    return r;
}
__device__ __forceinline__ float bfhf(float x) {
    return __bfloat162float(__float2bfloat16_rn(x));
}
__device__ __forceinline__ uint32_t smem_u32(const void* p) {
    return (uint32_t)__cvta_generic_to_shared(p);
}
__device__ __forceinline__ void cpa16(uint32_t dst, const void* src) {
    asm volatile("cp.async.cg.shared.global [%0], [%1], 16;" :: "r"(dst), "l"(src));
}
__device__ __forceinline__ void cpcommit() {
    asm volatile("cp.async.commit_group;" ::: "memory");
}
template <int N> __device__ __forceinline__ void cpwait() {
    asm volatile("cp.async.wait_group %0;" :: "n"(N) : "memory");
}

// ---------------------------------------------------------------------------
// Kernel 1: Wh = h @ W. 4 warps/CTA, 4 rows/warp register tile; h rows staged
// in smem (broadcast LDS.128), W via L1 (1 LDG.64 per k per warp, reused by
// 4 rows). Emits K-major bf16 hi/lo WhT + e1/e2.
// ---------------------------------------------------------------------------
__global__ void __launch_bounds__(128) wh_kernel(const float* __restrict__ h,
                                                 const float* __restrict__ W,
                                                 const float* __restrict__ a) {
    __shared__ float s_h[4][4][F_IN];   // 32 KB
    const int l = threadIdx.x & 31;
    const int w = threadIdx.x >> 5;
    const int r0 = blockIdx.x * 16 + w * 4;

#pragma unroll
    for (int r = 0; r < 4; ++r) {
        const float4* src = (const float4*)(h + (size_t)(r0 + r) * F_IN);
        float4* dst = (float4*)s_h[w][r];
        for (int t = l; t < F_IN / 4; t += 32) dst[t] = src[t];
    }
    __syncwarp();

    float ax[4] = {0.f, 0.f, 0.f, 0.f}, ay[4] = {0.f, 0.f, 0.f, 0.f};
    const float2* W2 = (const float2*)W;
    for (int k = 0; k < F_IN; k += 4) {
        float2 w0 = W2[(k + 0) * 32 + l];
        float2 w1 = W2[(k + 1) * 32 + l];
        float2 w2 = W2[(k + 2) * 32 + l];
        float2 w3 = W2[(k + 3) * 32 + l];
#pragma unroll
        for (int r = 0; r < 4; ++r) {
            float4 hv = *(const float4*)&s_h[w][r][k];
            ax[r] = fmaf(hv.x, w0.x, ax[r]); ay[r] = fmaf(hv.x, w0.y, ay[r]);
            ax[r] = fmaf(hv.y, w1.x, ax[r]); ay[r] = fmaf(hv.y, w1.y, ay[r]);
            ax[r] = fmaf(hv.z, w2.x, ax[r]); ay[r] = fmaf(hv.z, w2.y, ay[r]);
            ax[r] = fmaf(hv.w, w3.x, ax[r]); ay[r] = fmaf(hv.w, w3.y, ay[r]);
        }
    }

#pragma unroll
    for (int r = 0; r < 4; ++r) {
        const int i = r0 + r;
        __nv_bfloat16 hx = __float2bfloat16_rn(ax[r]);
        __nv_bfloat16 hy = __float2bfloat16_rn(ay[r]);
        g_WhT_hi[(size_t)(2 * l)     * NN + i] = hx;
        g_WhT_hi[(size_t)(2 * l + 1) * NN + i] = hy;
        g_WhT_lo[(size_t)(2 * l)     * NN + i] = __float2bfloat16_rn(ax[r] - __bfloat162float(hx));
        g_WhT_lo[(size_t)(2 * l + 1) * NN + i] = __float2bfloat16_rn(ay[r] - __bfloat162float(hy));

        float e1p = ax[r] * a[2 * l]        + ay[r] * a[2 * l + 1];
        float e2p = ax[r] * a[NOUT + 2 * l] + ay[r] * a[NOUT + 2 * l + 1];
#pragma unroll
        for (int off = 16; off; off >>= 1) {
            e1p += __shfl_xor_sync(0xffffffffu, e1p, off);
            e2p += __shfl_xor_sync(0xffffffffu, e2p, off);
        }
        if (l == 0) { g_e1[i] = e1p; g_e2[i] = e2p; }
    }
}

// ---------------------------------------------------------------------------
// Kernel 2: fused masked-exp + bf16 split GEMM via mma.sync.
// Grid 512 = 64 row-tiles(128 rows) x 8 j-splits; 128 threads / 4 warps;
// warp = 32 rows x 64 cols. B (WhT hi/lo) pipelined with cp.async, 3 stages
// of k=32; one __syncthreads per block. adj register-prefetched 1 chunk ahead.
// ---------------------------------------------------------------------------
__global__ void __launch_bounds__(128, 3) attn_kernel(const int* __restrict__ adj) {
    __shared__ float s_e2[JLEN];                          // 4 KB
    __shared__ __align__(16) char s_B[3][2][BBUF];        // 30 KB

    const int tid = threadIdx.x;
    const int w = tid >> 5;
    const int l = tid & 31;
    const int i0 = (int)(blockIdx.x >> 3) * 128;
    const int split = blockIdx.x & 7;
    const int j0 = split * JLEN;

    // stage e2 slice (visible after first in-loop __syncthreads)
    {
        float4* d = (float4*)s_e2;
        const float4* s = (const float4*)(g_e2 + j0);
        for (int k = tid; k < JLEN / 4; k += 128) d[k] = s[k];
    }

    const int rq = l >> 2;          // 0..7
    const int cq = (l & 3) * 2;     // 0,2,4,6

    float e1r[4];
    const int* rb[4];
#pragma unroll
    for (int k = 0; k < 4; ++k) {
        int row = i0 + w * 32 + 8 * k + rq;
        e1r[k] = g_e1[row];
        rb[k] = adj + (size_t)row * NN + j0 + cq;
    }

    const uint32_t sBs = smem_u32(&s_B[0][0][0]);
    // cp.async staging of B block blk into stage s (all 128 threads)
    auto stage = [&](int blk, int s) {
#pragma unroll
        for (int it = 0; it < 4; ++it) {
            int idx = it * 128 + tid;            // 0..511
            int hl = idx >> 8;                   // 0:hi 1:lo
            int rem = idx & 255;
            int c = rem >> 6;                    // 16B chunk 0..3 (8 bf16)
            int n = rem & 63;                    // n-row
            const __nv_bfloat16* src =
                (hl ? g_WhT_lo : g_WhT_hi) + (size_t)n * NN + j0 + blk * 32 + c * 8;
            cpa16(sBs + (uint32_t)((s * 2 + hl) * BBUF + n * BST + c * 16), src);
        }
    };

    // ldmatrix per-lane base
    const int g = l >> 3, lr = l & 7;
    const uint32_t sBm = sBs + (uint32_t)((lr + ((g >> 1) << 3)) * BST + ((g & 1) << 4));

    float acc[2][8][4];
#pragma unroll
    for (int t = 0; t < 2; ++t)
#pragma unroll
        for (int n = 0; n < 8; ++n)
#pragma unroll
            for (int q = 0; q < 4; ++q) acc[t][n][q] = 0.f;
    float den4[4] = {0.f, 0.f, 0.f, 0.f};

    // prime pipeline: B blocks 0,1; adj chunk 0
    stage(0, 0); cpcommit();
    stage(1, 1); cpcommit();
    int2 alo[4], ahi[4];
#pragma unroll
    for (int k = 0; k < 4; ++k) {
        alo[k] = *(const int2*)(rb[k]);
        ahi[k] = *(const int2*)(rb[k] + 8);
    }

    for (int blk = 0; blk < NBLK; ++blk) {
        const int s = blk % 3;
        if (blk + 1 < NBLK) cpwait<1>(); else cpwait<0>();
        __syncthreads();   // block blk's B visible; buffer (blk+2)%3 free
        if (blk + 2 < NBLK) { stage(blk + 2, (blk + 2) % 3); cpcommit(); }

#pragma unroll
        for (int c2 = 0; c2 < 2; ++c2) {
            const int ch = blk * 2 + c2;

            // ---- generate A fragments (P hi/lo) ----
            const float* e2p = s_e2 + ch * 16;
            float2 e2a = *(const float2*)(e2p + cq);
            float2 e2b = *(const float2*)(e2p + cq + 8);
            unsigned Ah[2][4], Al[2][4];
#pragma unroll
            for (int k = 0; k < 4; ++k) {
                const int t = k >> 1, rp = k & 1;
                const float e1v = e1r[k];
                float s0 = e1v + e2a.x; s0 = s0 > 0.f ? s0 : LRA * s0;
                float s1 = e1v + e2a.y; s1 = s1 > 0.f ? s1 : LRA * s1;
                float s2 = e1v + e2b.x; s2 = s2 > 0.f ? s2 : LRA * s2;
                float s3 = e1v + e2b.y; s3 = s3 > 0.f ? s3 : LRA * s3;
                float p0 = alo[k].x > 0 ? __expf(s0) : 0.f;
                float p1 = alo[k].y > 0 ? __expf(s1) : 0.f;
                float p2 = ahi[k].x > 0 ? __expf(s2) : 0.f;
                float p3 = ahi[k].y > 0 ? __expf(s3) : 0.f;
                den4[k] += (p0 + p1) + (p2 + p3);
                float h0 = bfhf(p0), h1 = bfhf(p1), h2 = bfhf(p2), h3 = bfhf(p3);
                Ah[t][rp]     = cvt2(h1, h0);
                Ah[t][rp + 2] = cvt2(h3, h2);
                Al[t][rp]     = cvt2(p1 - h1, p0 - h0);
                Al[t][rp + 2] = cvt2(p3 - h3, p2 - h2);
            }

            // ---- prefetch next chunk's adj ----
            if (ch + 1 < NCH) {
#pragma unroll
                for (int k = 0; k < 4; ++k) {
                    alo[k] = *(const int2*)(rb[k] + (ch + 1) * 16);
                    ahi[k] = *(const int2*)(rb[k] + (ch + 1) * 16 + 8);
                }
            }

            // ---- B hi fragments + products ----
            const uint32_t bo_hi = (uint32_t)((s * 2) * BBUF + c2 * 32);
            unsigned Bh[8][2];
#pragma unroll
            for (int np = 0; np < 4; ++np)
                ldsm4(&Bh[2 * np][0], sBm + bo_hi + np * (16 * BST));
#pragma unroll
            for (int t = 0; t < 2; ++t)
#pragma unroll
                for (int n = 0; n < 8; ++n) mma16816(acc[t][n], Ah[t], Bh[n]);
#pragma unroll
            for (int t = 0; t < 2; ++t)
#pragma unroll
                for (int n = 0; n < 8; ++n) mma16816(acc[t][n], Al[t], Bh[n]);

            // ---- B lo fragments + product ----
            const uint32_t bo_lo = (uint32_t)((s * 2 + 1) * BBUF + c2 * 32);
            unsigned Bl[8][2];
#pragma unroll
            for (int np = 0; np < 4; ++np)
                ldsm4(&Bl[2 * np][0], sBm + bo_lo + np * (16 * BST));
#pragma unroll
            for (int t = 0; t < 2; ++t)
#pragma unroll
                for (int n = 0; n < 8; ++n) mma16816(acc[t][n], Ah[t], Bl[n]);
        }
    }

    // ---- denominators: quad-reduce per row ----
#pragma unroll
    for (int k = 0; k < 4; ++k) {
        den4[k] += __shfl_xor_sync(0xffffffffu, den4[k], 1);
        den4[k] += __shfl_xor_sync(0xffffffffu, den4[k], 2);
    }
    if ((l & 3) == 0) {
#pragma unroll
        for (int k = 0; k < 4; ++k)
            g_pden[split][i0 + w * 32 + 8 * k + rq] = den4[k];
    }

    // ---- write fp32 partial numerators ----
#pragma unroll
    for (int t = 0; t < 2; ++t) {
        const int row = i0 + w * 32 + t * 16 + rq;
#pragma unroll
        for (int n = 0; n < 8; ++n) {
            *(float2*)&g_pacc[split][row][n * 8 + cq]     = make_float2(acc[t][n][0], acc[t][n][1]);
            *(float2*)&g_pacc[split][row + 8][n * 8 + cq] = make_float2(acc[t][n][2], acc[t][n][3]);
        }
    }
}

// ---------------------------------------------------------------------------
// Kernel 3: combine splits, normalize, ELU.
// ---------------------------------------------------------------------------
__global__ void __launch_bounds__(256) combine_kernel(float* __restrict__ out) {
    const int idx = blockIdx.x * 256 + threadIdx.x;   // over 8192*64
    const int i = idx >> 6;
    const int c = idx & 63;
    float acc = 0.f, den = 0.f;
#pragma unroll
    for (int sp = 0; sp < JSPLITS; ++sp) {
        acc += g_pacc[sp][i][c];
        den += g_pden[sp][i];
    }
    if (den == 0.f) den = 1.f;
    float v = acc / den;
    out[idx] = v > 0.f ? v : expm1f(v);
}

// ---------------------------------------------------------------------------
extern "C" void kernel_launch(void* const* d_in, const int* in_sizes, int n_in,
                              void* d_out, int out_size) {
    const float* h   = (const float*)d_in[0];
    const float* W   = (const float*)d_in[1];
    const float* a   = (const float*)d_in[2];
    const int*   adj = (const int*)d_in[3];
    float* out = (float*)d_out;

    wh_kernel<<<NN / 16, 128>>>(h, W, a);
    attn_kernel<<<(NN / 128) * JSPLITS, 128>>>(adj);
    combine_kernel<<<NN * NOUT / 256, 256>>>(out);
}

// round 5
// speedup vs baseline: 9.3116x; 1.3058x over previous
#include <cuda_runtime.h>
#include <cuda_bf16.h>
#include <cstdint>

#define NN      8192
#define F_IN    512
#define NOUT    64
#define LRA     0.2f
#define JSPLITS 8
#define JLEN    (NN / JSPLITS)     // 1024
#define NCH     (JLEN / 16)        // 64 chunks of k=16
#define NBLK    (NCH / 2)          // 32 blocks of k=32
#define BST     80                 // padded bytes per n-row in staged B
#define BBUF    (64 * BST)         // 5120 B per (stage,hi/lo)

// ---------------- device scratch (no cudaMalloc allowed) -------------------
__device__ __align__(16) __nv_bfloat16 g_WhT_hi[NOUT * NN];  // [n][k] K-major
__device__ __align__(16) __nv_bfloat16 g_WhT_lo[NOUT * NN];
__device__ float g_e1[NN];
__device__ float g_e2[NN];
__device__ float g_pacc[JSPLITS][NN][NOUT];
__device__ float g_pden[JSPLITS][NN];

// ---------------- helpers ---------------------------------------------------
__device__ __forceinline__ void mma16816(float* d, const unsigned* a, const unsigned* b) {
    asm volatile(
        "mma.sync.aligned.m16n8k16.row.col.f32.bf16.bf16.f32 "
        "{%0,%1,%2,%3}, {%4,%5,%6,%7}, {%8,%9}, {%0,%1,%2,%3};"
        : "+f"(d[0]), "+f"(d[1]), "+f"(d[2]), "+f"(d[3])
        : "r"(a[0]), "r"(a[1]), "r"(a[2]), "r"(a[3]), "r"(b[0]), "r"(b[1]));
}
__device__ __forceinline__ void ldsm4(unsigned* r, uint32_t addr) {
    asm volatile("ldmatrix.sync.aligned.m8n8.x4.shared.b16 {%0,%1,%2,%3}, [%4];"
                 : "=r"(r[0]), "=r"(r[1]), "=r"(r[2]), "=r"(r[3]) : "r"(addr));
}
__device__ __forceinline__ unsigned cvt2(float po, float pe) {   // hi=po, lo=pe
    unsigned r;
    asm("cvt.rn.bf16x2.f32 %0, %1, %2;" : "=r"(r) : "f"(po), "f"(pe));
    return r;
}
__device__ __forceinline__ float bfhf(float x) {
    return __bfloat162float(__float2bfloat16_rn(x));
}
__device__ __forceinline__ uint32_t smem_u32(const void* p) {
    return (uint32_t)__cvta_generic_to_shared(p);
}
__device__ __forceinline__ void cpa16(uint32_t dst, const void* src) {
    asm volatile("cp.async.cg.shared.global [%0], [%1], 16;" :: "r"(dst), "l"(src));
}
__device__ __forceinline__ void cpcommit() {
    asm volatile("cp.async.commit_group;" ::: "memory");
}
template <int N> __device__ __forceinline__ void cpwait() {
    asm volatile("cp.async.wait_group %0;" :: "n"(N) : "memory");
}

// ---------------------------------------------------------------------------
// Kernel 1: Wh = h @ W. 4 warps/CTA, 4 rows/warp; W and h register
// double-buffered one k-4 step ahead so FFMAs never wait on fresh loads.
// Emits K-major bf16 hi/lo WhT + e1/e2.
// ---------------------------------------------------------------------------
__global__ void __launch_bounds__(128) wh_kernel(const float* __restrict__ h,
                                                 const float* __restrict__ W,
                                                 const float* __restrict__ a) {
    __shared__ float s_h[4][4][F_IN];   // 32 KB
    const int l = threadIdx.x & 31;
    const int w = threadIdx.x >> 5;
    const int r0 = blockIdx.x * 16 + w * 4;

#pragma unroll
    for (int r = 0; r < 4; ++r) {
        const float4* src = (const float4*)(h + (size_t)(r0 + r) * F_IN);
        float4* dst = (float4*)s_h[w][r];
        for (int t = l; t < F_IN / 4; t += 32) dst[t] = src[t];
    }
    __syncwarp();

    const float2* W2 = (const float2*)W;
    float2 wreg[2][4];
    float4 hreg[2][4];
#pragma unroll
    for (int s = 0; s < 2; ++s) {
#pragma unroll
        for (int q = 0; q < 4; ++q) wreg[s][q] = W2[(s * 4 + q) * 32 + l];
#pragma unroll
        for (int r = 0; r < 4; ++r) hreg[s][r] = *(const float4*)&s_h[w][r][s * 4];
    }

    float ax[4] = {0.f, 0.f, 0.f, 0.f}, ay[4] = {0.f, 0.f, 0.f, 0.f};
#pragma unroll 2
    for (int k = 0; k < F_IN; k += 4) {
        const int cur = (k >> 2) & 1;
        float2 w0 = wreg[cur][0], w1 = wreg[cur][1], w2 = wreg[cur][2], w3 = wreg[cur][3];
        float4 hv0 = hreg[cur][0], hv1 = hreg[cur][1], hv2 = hreg[cur][2], hv3 = hreg[cur][3];
        if (k + 8 < F_IN) {
#pragma unroll
            for (int q = 0; q < 4; ++q) wreg[cur][q] = W2[(k + 8 + q) * 32 + l];
#pragma unroll
            for (int r = 0; r < 4; ++r) hreg[cur][r] = *(const float4*)&s_h[w][r][k + 8];
        }
        ax[0] = fmaf(hv0.x, w0.x, ax[0]); ay[0] = fmaf(hv0.x, w0.y, ay[0]);
        ax[0] = fmaf(hv0.y, w1.x, ax[0]); ay[0] = fmaf(hv0.y, w1.y, ay[0]);
        ax[0] = fmaf(hv0.z, w2.x, ax[0]); ay[0] = fmaf(hv0.z, w2.y, ay[0]);
        ax[0] = fmaf(hv0.w, w3.x, ax[0]); ay[0] = fmaf(hv0.w, w3.y, ay[0]);
        ax[1] = fmaf(hv1.x, w0.x, ax[1]); ay[1] = fmaf(hv1.x, w0.y, ay[1]);
        ax[1] = fmaf(hv1.y, w1.x, ax[1]); ay[1] = fmaf(hv1.y, w1.y, ay[1]);
        ax[1] = fmaf(hv1.z, w2.x, ax[1]); ay[1] = fmaf(hv1.z, w2.y, ay[1]);
        ax[1] = fmaf(hv1.w, w3.x, ax[1]); ay[1] = fmaf(hv1.w, w3.y, ay[1]);
        ax[2] = fmaf(hv2.x, w0.x, ax[2]); ay[2] = fmaf(hv2.x, w0.y, ay[2]);
        ax[2] = fmaf(hv2.y, w1.x, ax[2]); ay[2] = fmaf(hv2.y, w1.y, ay[2]);
        ax[2] = fmaf(hv2.z, w2.x, ax[2]); ay[2] = fmaf(hv2.z, w2.y, ay[2]);
        ax[2] = fmaf(hv2.w, w3.x, ax[2]); ay[2] = fmaf(hv2.w, w3.y, ay[2]);
        ax[3] = fmaf(hv3.x, w0.x, ax[3]); ay[3] = fmaf(hv3.x, w0.y, ay[3]);
        ax[3] = fmaf(hv3.y, w1.x, ax[3]); ay[3] = fmaf(hv3.y, w1.y, ay[3]);
        ax[3] = fmaf(hv3.z, w2.x, ax[3]); ay[3] = fmaf(hv3.z, w2.y, ay[3]);
        ax[3] = fmaf(hv3.w, w3.x, ax[3]); ay[3] = fmaf(hv3.w, w3.y, ay[3]);
    }

#pragma unroll
    for (int r = 0; r < 4; ++r) {
        const int i = r0 + r;
        __nv_bfloat16 hx = __float2bfloat16_rn(ax[r]);
        __nv_bfloat16 hy = __float2bfloat16_rn(ay[r]);
        g_WhT_hi[(size_t)(2 * l)     * NN + i] = hx;
        g_WhT_hi[(size_t)(2 * l + 1) * NN + i] = hy;
        g_WhT_lo[(size_t)(2 * l)     * NN + i] = __float2bfloat16_rn(ax[r] - __bfloat162float(hx));
        g_WhT_lo[(size_t)(2 * l + 1) * NN + i] = __float2bfloat16_rn(ay[r] - __bfloat162float(hy));

        float e1p = ax[r] * a[2 * l]        + ay[r] * a[2 * l + 1];
        float e2p = ax[r] * a[NOUT + 2 * l] + ay[r] * a[NOUT + 2 * l + 1];
#pragma unroll
        for (int off = 16; off; off >>= 1) {
            e1p += __shfl_xor_sync(0xffffffffu, e1p, off);
            e2p += __shfl_xor_sync(0xffffffffu, e2p, off);
        }
        if (l == 0) { g_e1[i] = e1p; g_e2[i] = e2p; }
    }
}

// ---------------------------------------------------------------------------
// Kernel 2: fused masked-exp + bf16 split GEMM via mma.sync.
// Grid 512 = 64 row-tiles(128 rows) x 8 j-splits; 256 threads / 8 warps;
// warp = 16 rows x 64 cols (32 acc regs -> 2 CTAs/SM, 4 warps/SMSP).
// B pipelined with cp.async (3 stages of k=32); adj prefetched 1 chunk ahead.
// ---------------------------------------------------------------------------
__global__ void __launch_bounds__(256, 2) attn_kernel(const int* __restrict__ adj) {
    __shared__ float s_e2[JLEN];                          // 4 KB
    __shared__ __align__(16) char s_B[3][2][BBUF];        // 30 KB

    const int tid = threadIdx.x;
    const int w = tid >> 5;
    const int l = tid & 31;
    const int i0 = (int)(blockIdx.x >> 3) * 128;
    const int split = blockIdx.x & 7;
    const int j0 = split * JLEN;

    // stage e2 slice (visible after first in-loop __syncthreads)
    {
        float4* d = (float4*)s_e2;
        const float4* s = (const float4*)(g_e2 + j0);
        for (int k = tid; k < JLEN / 4; k += 256) d[k] = s[k];
    }

    const int rq = l >> 2;          // 0..7
    const int cq = (l & 3) * 2;     // 0,2,4,6

    float e1r[2];
    const int* rb[2];
#pragma unroll
    for (int k = 0; k < 2; ++k) {
        int row = i0 + w * 16 + 8 * k + rq;
        e1r[k] = g_e1[row];
        rb[k] = adj + (size_t)row * NN + j0 + cq;
    }

    const uint32_t sBs = smem_u32(&s_B[0][0][0]);
    // cp.async staging of B block blk into stage s (all 256 threads)
    auto stage = [&](int blk, int s) {
#pragma unroll
        for (int it = 0; it < 2; ++it) {
            int idx = it * 256 + tid;            // 0..511
            int hl = idx >> 8;                   // 0:hi 1:lo
            int rem = idx & 255;
            int c = rem >> 6;                    // 16B chunk 0..3 (8 bf16)
            int n = rem & 63;                    // n-row
            const __nv_bfloat16* src =
                (hl ? g_WhT_lo : g_WhT_hi) + (size_t)n * NN + j0 + blk * 32 + c * 8;
            cpa16(sBs + (uint32_t)((s * 2 + hl) * BBUF + n * BST + c * 16), src);
        }
    };

    // ldmatrix per-lane base
    const int g = l >> 3, lr = l & 7;
    const uint32_t sBm = sBs + (uint32_t)((lr + ((g >> 1) << 3)) * BST + ((g & 1) << 4));

    float acc[8][4];
#pragma unroll
    for (int n = 0; n < 8; ++n)
#pragma unroll
        for (int q = 0; q < 4; ++q) acc[n][q] = 0.f;
    float den2[2] = {0.f, 0.f};

    // prime pipeline
    stage(0, 0); cpcommit();
    stage(1, 1); cpcommit();
    int2 alo[2], ahi[2];
#pragma unroll
    for (int k = 0; k < 2; ++k) {
        alo[k] = *(const int2*)(rb[k]);
        ahi[k] = *(const int2*)(rb[k] + 8);
    }

    for (int blk = 0; blk < NBLK; ++blk) {
        const int s = blk % 3;
        if (blk + 1 < NBLK) cpwait<1>(); else cpwait<0>();
        __syncthreads();   // block blk's B visible; buffer (blk+2)%3 free
        if (blk + 2 < NBLK) { stage(blk + 2, (blk + 2) % 3); cpcommit(); }

#pragma unroll
        for (int c2 = 0; c2 < 2; ++c2) {
            const int ch = blk * 2 + c2;

            // ---- generate A fragments (P hi/lo) ----
            const float* e2p = s_e2 + ch * 16;
            float2 e2a = *(const float2*)(e2p + cq);
            float2 e2b = *(const float2*)(e2p + cq + 8);
            unsigned Ah[4], Al[4];
#pragma unroll
            for (int k = 0; k < 2; ++k) {
                const float e1v = e1r[k];
                float s0 = e1v + e2a.x; s0 = s0 > 0.f ? s0 : LRA * s0;
                float s1 = e1v + e2a.y; s1 = s1 > 0.f ? s1 : LRA * s1;
                float s2 = e1v + e2b.x; s2 = s2 > 0.f ? s2 : LRA * s2;
                float s3 = e1v + e2b.y; s3 = s3 > 0.f ? s3 : LRA * s3;
                float p0 = alo[k].x > 0 ? __expf(s0) : 0.f;
                float p1 = alo[k].y > 0 ? __expf(s1) : 0.f;
                float p2 = ahi[k].x > 0 ? __expf(s2) : 0.f;
                float p3 = ahi[k].y > 0 ? __expf(s3) : 0.f;
                den2[k] += (p0 + p1) + (p2 + p3);
                float h0 = bfhf(p0), h1 = bfhf(p1), h2 = bfhf(p2), h3 = bfhf(p3);
                Ah[k]     = cvt2(h1, h0);
                Ah[k + 2] = cvt2(h3, h2);
                Al[k]     = cvt2(p1 - h1, p0 - h0);
                Al[k + 2] = cvt2(p3 - h3, p2 - h2);
            }

            // ---- prefetch next chunk's adj ----
            if (ch + 1 < NCH) {
#pragma unroll
                for (int k = 0; k < 2; ++k) {
                    alo[k] = *(const int2*)(rb[k] + (ch + 1) * 16);
                    ahi[k] = *(const int2*)(rb[k] + (ch + 1) * 16 + 8);
                }
            }

            // ---- B hi fragments + products ----
            const uint32_t bo_hi = (uint32_t)((s * 2) * BBUF + c2 * 32);
            unsigned Bh[8][2];
#pragma unroll
            for (int np = 0; np < 4; ++np)
                ldsm4(&Bh[2 * np][0], sBm + bo_hi + np * (16 * BST));
#pragma unroll
            for (int n = 0; n < 8; ++n) mma16816(acc[n], Ah, Bh[n]);
#pragma unroll
            for (int n = 0; n < 8; ++n) mma16816(acc[n], Al, Bh[n]);

            // ---- B lo fragments + product ----
            const uint32_t bo_lo = (uint32_t)((s * 2 + 1) * BBUF + c2 * 32);
            unsigned Bl[8][2];
#pragma unroll
            for (int np = 0; np < 4; ++np)
                ldsm4(&Bl[2 * np][0], sBm + bo_lo + np * (16 * BST));
#pragma unroll
            for (int n = 0; n < 8; ++n) mma16816(acc[n], Ah, Bl[n]);
        }
    }

    // ---- denominators: quad-reduce per row ----
#pragma unroll
    for (int k = 0; k < 2; ++k) {
        den2[k] += __shfl_xor_sync(0xffffffffu, den2[k], 1);
        den2[k] += __shfl_xor_sync(0xffffffffu, den2[k], 2);
    }
    if ((l & 3) == 0) {
        g_pden[split][i0 + w * 16 + rq]     = den2[0];
        g_pden[split][i0 + w * 16 + 8 + rq] = den2[1];
    }

    // ---- write fp32 partial numerators ----
    {
        const int row = i0 + w * 16 + rq;
#pragma unroll
        for (int n = 0; n < 8; ++n) {
            *(float2*)&g_pacc[split][row][n * 8 + cq]     = make_float2(acc[n][0], acc[n][1]);
            *(float2*)&g_pacc[split][row + 8][n * 8 + cq] = make_float2(acc[n][2], acc[n][3]);
        }
    }
}

// ---------------------------------------------------------------------------
// Kernel 3: combine splits, normalize, ELU.
// ---------------------------------------------------------------------------
__global__ void __launch_bounds__(256) combine_kernel(float* __restrict__ out) {
    const int idx = blockIdx.x * 256 + threadIdx.x;   // over 8192*64
    const int i = idx >> 6;
    const int c = idx & 63;
    float acc = 0.f, den = 0.f;
#pragma unroll
    for (int sp = 0; sp < JSPLITS; ++sp) {
        acc += g_pacc[sp][i][c];
        den += g_pden[sp][i];
    }
    if (den == 0.f) den = 1.f;
    float v = acc / den;
    out[idx] = v > 0.f ? v : expm1f(v);
}

// ---------------------------------------------------------------------------
extern "C" void kernel_launch(void* const* d_in, const int* in_sizes, int n_in,
                              void* d_out, int out_size) {
    const float* h   = (const float*)d_in[0];
    const float* W   = (const float*)d_in[1];
    const float* a   = (const float*)d_in[2];
    const int*   adj = (const int*)d_in[3];
    float* out = (float*)d_out;

    wh_kernel<<<NN / 16, 128>>>(h, W, a);
    attn_kernel<<<(NN / 128) * JSPLITS, 256>>>(adj);
    combine_kernel<<<NN * NOUT / 256, 256>>>(out);
}

// round 6
// speedup vs baseline: 10.3802x; 1.1148x over previous
#include <cuda_runtime.h>
#include <cuda_bf16.h>
#include <cstdint>

#define NN      8192
#define F_IN    512
#define NOUT    64
#define LRA     0.2f
#define JSPLITS 8
#define JLEN    (NN / JSPLITS)     // 1024
#define NCH     (JLEN / 16)        // 64 chunks of k=16

// ---------------- device scratch (no cudaMalloc allowed) -------------------
// Fragment-packed W (B-operand of wh GEMM): [64 n][32 kchunk][4 s] uint4,
// uint4 = {hi(k0,k0+1), hi(k0+8,k0+9), lo(k0,k0+1), lo(k0+8,k0+9)}, k0=chg*16+2s
__device__ uint4 g_W_pk[64 * 32 * 4];         // 128 KB
// Fragment-packed WhT (B-operand of attn GEMM): [64 n][512 jchunk][4 s] uint4
__device__ uint4 g_WhT_pk[64 * 512 * 4];      // 2 MB
__device__ float g_e1[NN];
__device__ float g_e2[NN];
__device__ float g_pacc[JSPLITS][NN][NOUT];
__device__ float g_pden[JSPLITS][NN];

// ---------------- helpers ---------------------------------------------------
__device__ __forceinline__ void mma16816(float* d, const unsigned* a,
                                         unsigned b0, unsigned b1) {
    asm volatile(
        "mma.sync.aligned.m16n8k16.row.col.f32.bf16.bf16.f32 "
        "{%0,%1,%2,%3}, {%4,%5,%6,%7}, {%8,%9}, {%0,%1,%2,%3};"
        : "+f"(d[0]), "+f"(d[1]), "+f"(d[2]), "+f"(d[3])
        : "r"(a[0]), "r"(a[1]), "r"(a[2]), "r"(a[3]), "r"(b0), "r"(b1));
}
__device__ __forceinline__ unsigned cvt2(float po, float pe) {   // hi=po, lo=pe
    unsigned r;
    asm("cvt.rn.bf16x2.f32 %0, %1, %2;" : "=r"(r) : "f"(po), "f"(pe));
    return r;
}
__device__ __forceinline__ float bfhf(float x) {
    return __bfloat162float(__float2bfloat16_rn(x));
}
__device__ __forceinline__ uint32_t smem_u32(const void* p) {
    return (uint32_t)__cvta_generic_to_shared(p);
}
__device__ __forceinline__ void cpa16(uint32_t dst, const void* src) {
    asm volatile("cp.async.cg.shared.global [%0], [%1], 16;" :: "r"(dst), "l"(src));
}
__device__ __forceinline__ void cpcommit() {
    asm volatile("cp.async.commit_group;" ::: "memory");
}
template <int N> __device__ __forceinline__ void cpwait() {
    asm volatile("cp.async.wait_group %0;" :: "n"(N) : "memory");
}

// ---------------------------------------------------------------------------
// Kernel 0: pack W (fp32 [512][64]) into bf16 hi/lo fragment layout.
// 8192 threads: t -> (n, kchunk, s).
// ---------------------------------------------------------------------------
__global__ void __launch_bounds__(256) prep_w(const float* __restrict__ W) {
    const int t = blockIdx.x * 256 + threadIdx.x;
    const int s = t & 3, kc = (t >> 2) & 31, n = t >> 7;
    const int k0 = kc * 16 + 2 * s;
    float v00 = W[(k0 + 0) * 64 + n], v01 = W[(k0 + 1) * 64 + n];
    float v10 = W[(k0 + 8) * 64 + n], v11 = W[(k0 + 9) * 64 + n];
    float h00 = bfhf(v00), h01 = bfhf(v01), h10 = bfhf(v10), h11 = bfhf(v11);
    uint4 o;
    o.x = cvt2(h01, h00);
    o.y = cvt2(h11, h10);
    o.z = cvt2(v01 - h01, v00 - h00);
    o.w = cvt2(v11 - h11, v10 - h10);
    g_W_pk[(n * 32 + kc) * 4 + s] = o;
}

// ---------------------------------------------------------------------------
// Kernel 1: Wh = h @ W via mma.sync (3-product bf16 split).
// Grid 128, 128 thr / 4 warps; CTA = 64 nodes; warp = 16 nodes x 64 outcols.
// h tiles via 3-stage cp.async (fp32), converted to frags in-register;
// W from g_W_pk (1 LDG.128 per n-tile per kchunk, L1-resident).
// Epilogue: e1/e2 + WhT_pk via smem transpose.
// ---------------------------------------------------------------------------
__global__ void __launch_bounds__(128, 1) wh_mma(const float* __restrict__ h,
                                                 const float* __restrict__ a) {
    __shared__ float s_h[3][64][20];    // 80B rows: cp.async-aligned, conflict-free
    __shared__ float s_t[64][65];       // transpose buffer

    const int tid = threadIdx.x;
    const int w = tid >> 5;
    const int l = tid & 31;
    const int r = l >> 2;          // 0..7
    const int c = (l & 3) * 2;     // 0,2,4,6
    const int node0 = blockIdx.x * 64;

    const uint32_t shb = smem_u32(&s_h[0][0][0]);
    auto stage = [&](int kc, int s) {
        const int row = tid >> 1, half = tid & 1;
        const float* src = h + (size_t)(node0 + row) * F_IN + kc * 16 + half * 8;
        uint32_t dst = shb + (uint32_t)((s * 64 + row) * 20 + half * 8) * 4;
        cpa16(dst, src);
        cpa16(dst + 16, src + 4);
    };

    stage(0, 0); cpcommit();
    stage(1, 1); cpcommit();

    float acc[8][4];
#pragma unroll
    for (int n = 0; n < 8; ++n)
#pragma unroll
        for (int q = 0; q < 4; ++q) acc[n][q] = 0.f;

    const uint4* __restrict__ wpk = g_W_pk;

    for (int kc = 0; kc < 32; ++kc) {
        const int ss = kc % 3;
        if (kc + 1 < 32) cpwait<1>(); else cpwait<0>();
        __syncthreads();
        if (kc + 2 < 32) { stage(kc + 2, (kc + 2) % 3); cpcommit(); }

        // B frags (W packed)
        uint4 B4[8];
#pragma unroll
        for (int nt = 0; nt < 8; ++nt)
            B4[nt] = wpk[((nt * 8 + r) * 32 + kc) * 4 + (l & 3)];

        // A frags from fp32 h tile
        float2 v0 = *(const float2*)&s_h[ss][w * 16 + r][c];
        float2 v1 = *(const float2*)&s_h[ss][w * 16 + r + 8][c];
        float2 v2 = *(const float2*)&s_h[ss][w * 16 + r][c + 8];
        float2 v3 = *(const float2*)&s_h[ss][w * 16 + r + 8][c + 8];
        float h0x = bfhf(v0.x), h0y = bfhf(v0.y);
        float h1x = bfhf(v1.x), h1y = bfhf(v1.y);
        float h2x = bfhf(v2.x), h2y = bfhf(v2.y);
        float h3x = bfhf(v3.x), h3y = bfhf(v3.y);
        unsigned Ah[4], Al[4];
        Ah[0] = cvt2(h0y, h0x); Al[0] = cvt2(v0.y - h0y, v0.x - h0x);
        Ah[1] = cvt2(h1y, h1x); Al[1] = cvt2(v1.y - h1y, v1.x - h1x);
        Ah[2] = cvt2(h2y, h2x); Al[2] = cvt2(v2.y - h2y, v2.x - h2x);
        Ah[3] = cvt2(h3y, h3x); Al[3] = cvt2(v3.y - h3y, v3.x - h3x);

#pragma unroll
        for (int nt = 0; nt < 8; ++nt) mma16816(acc[nt], Ah, B4[nt].x, B4[nt].y);
#pragma unroll
        for (int nt = 0; nt < 8; ++nt) mma16816(acc[nt], Al, B4[nt].x, B4[nt].y);
#pragma unroll
        for (int nt = 0; nt < 8; ++nt) mma16816(acc[nt], Ah, B4[nt].z, B4[nt].w);
    }

    // ---- e1/e2 ----
    {
        float e1p0 = 0.f, e1p8 = 0.f, e2p0 = 0.f, e2p8 = 0.f;
#pragma unroll
        for (int nt = 0; nt < 8; ++nt) {
            float2 a1v = *(const float2*)&a[nt * 8 + c];
            float2 a2v = *(const float2*)&a[NOUT + nt * 8 + c];
            e1p0 += acc[nt][0] * a1v.x + acc[nt][1] * a1v.y;
            e1p8 += acc[nt][2] * a1v.x + acc[nt][3] * a1v.y;
            e2p0 += acc[nt][0] * a2v.x + acc[nt][1] * a2v.y;
            e2p8 += acc[nt][2] * a2v.x + acc[nt][3] * a2v.y;
        }
#pragma unroll
        for (int off = 1; off <= 2; off <<= 1) {
            e1p0 += __shfl_xor_sync(0xffffffffu, e1p0, off);
            e1p8 += __shfl_xor_sync(0xffffffffu, e1p8, off);
            e2p0 += __shfl_xor_sync(0xffffffffu, e2p0, off);
            e2p8 += __shfl_xor_sync(0xffffffffu, e2p8, off);
        }
        if ((l & 3) == 0) {
            g_e1[node0 + w * 16 + r]     = e1p0;
            g_e1[node0 + w * 16 + r + 8] = e1p8;
            g_e2[node0 + w * 16 + r]     = e2p0;
            g_e2[node0 + w * 16 + r + 8] = e2p8;
        }
    }

    // ---- transpose to smem, then pack WhT_pk ----
    __syncthreads();
#pragma unroll
    for (int nt = 0; nt < 8; ++nt) {
        s_t[w * 16 + r][nt * 8 + c]         = acc[nt][0];
        s_t[w * 16 + r][nt * 8 + c + 1]     = acc[nt][1];
        s_t[w * 16 + r + 8][nt * 8 + c]     = acc[nt][2];
        s_t[w * 16 + r + 8][nt * 8 + c + 1] = acc[nt][3];
    }
    __syncthreads();

    {
        const int col = tid >> 1, nh = tid & 1;
        float f[32];
#pragma unroll
        for (int j = 0; j < 32; ++j) f[j] = s_t[nh * 32 + j][col];
#pragma unroll
        for (int q = 0; q < 2; ++q) {
            const int chg = blockIdx.x * 4 + nh * 2 + q;
            const int jo = q * 16;
#pragma unroll
            for (int s = 0; s < 4; ++s) {
                float f0 = f[jo + 2 * s],     f1 = f[jo + 2 * s + 1];
                float f8 = f[jo + 2 * s + 8], f9 = f[jo + 2 * s + 9];
                float g0 = bfhf(f0), g1 = bfhf(f1), g8 = bfhf(f8), g9 = bfhf(f9);
                uint4 o;
                o.x = cvt2(g1, g0);
                o.y = cvt2(g9, g8);
                o.z = cvt2(f1 - g1, f0 - g0);
                o.w = cvt2(f9 - g9, f8 - g8);
                g_WhT_pk[(col * 512 + chg) * 4 + s] = o;
            }
        }
    }
}

// ---------------------------------------------------------------------------
// Kernel 2: fused masked-exp + bf16 split GEMM, barrier-free main loop.
// Grid 512 = 64 row-tiles(128) x 8 j-splits; 256 thr / 8 warps;
// warp = 16 rows x 64 cols. B = 1 LDG.128 per n-tile per chunk from g_WhT_pk
// (L1-resident, shared by all warps); adj register-prefetched 1 chunk ahead.
// ---------------------------------------------------------------------------
__global__ void __launch_bounds__(256, 2) attn_kernel(const int* __restrict__ adj) {
    __shared__ float s_e2[JLEN];    // 4 KB

    const int tid = threadIdx.x;
    const int w = tid >> 5;
    const int l = tid & 31;
    const int i0 = (int)(blockIdx.x >> 3) * 128;
    const int split = blockIdx.x & 7;
    const int j0 = split * JLEN;

    {
        float4* d = (float4*)s_e2;
        const float4* s = (const float4*)(g_e2 + j0);
        for (int k = tid; k < JLEN / 4; k += 256) d[k] = s[k];
    }

    const int rq = l >> 2;          // 0..7
    const int cq = (l & 3) * 2;     // 0,2,4,6

    float e1r[2];
    const int* rb[2];
#pragma unroll
    for (int k = 0; k < 2; ++k) {
        int row = i0 + w * 16 + 8 * k + rq;
        e1r[k] = g_e1[row];
        rb[k] = adj + (size_t)row * NN + j0 + cq;
    }

    // per-lane B pointer: uint4 index = (n*512 + chg)*4 + (l&3), n = nt*8 + l/4
    const uint4* __restrict__ bp =
        g_WhT_pk + (size_t)rq * 2048 + (l & 3) + (size_t)split * 256;

    float acc[8][4];
#pragma unroll
    for (int n = 0; n < 8; ++n)
#pragma unroll
        for (int q = 0; q < 4; ++q) acc[n][q] = 0.f;
    float den2[2] = {0.f, 0.f};

    int2 alo[2], ahi[2];
#pragma unroll
    for (int k = 0; k < 2; ++k) {
        alo[k] = *(const int2*)(rb[k]);
        ahi[k] = *(const int2*)(rb[k] + 8);
    }
    __syncthreads();   // e2 visible; only barrier in the kernel

    for (int ch = 0; ch < NCH; ++ch) {
        // ---- B frags: 8 x LDG.128 ----
        uint4 B4[8];
#pragma unroll
        for (int nt = 0; nt < 8; ++nt) B4[nt] = bp[nt * 16384 + ch * 4];

        // ---- generate A fragments (P hi/lo) ----
        const float* e2p = s_e2 + ch * 16;
        float2 e2a = *(const float2*)(e2p + cq);
        float2 e2b = *(const float2*)(e2p + cq + 8);
        unsigned Ah[4], Al[4];
#pragma unroll
        for (int k = 0; k < 2; ++k) {
            const float e1v = e1r[k];
            float s0 = e1v + e2a.x; s0 = s0 > 0.f ? s0 : LRA * s0;
            float s1 = e1v + e2a.y; s1 = s1 > 0.f ? s1 : LRA * s1;
            float s2 = e1v + e2b.x; s2 = s2 > 0.f ? s2 : LRA * s2;
            float s3 = e1v + e2b.y; s3 = s3 > 0.f ? s3 : LRA * s3;
            float p0 = alo[k].x > 0 ? __expf(s0) : 0.f;
            float p1 = alo[k].y > 0 ? __expf(s1) : 0.f;
            float p2 = ahi[k].x > 0 ? __expf(s2) : 0.f;
            float p3 = ahi[k].y > 0 ? __expf(s3) : 0.f;
            den2[k] += (p0 + p1) + (p2 + p3);
            float h0 = bfhf(p0), h1 = bfhf(p1), h2 = bfhf(p2), h3 = bfhf(p3);
            Ah[k]     = cvt2(h1, h0);
            Ah[k + 2] = cvt2(h3, h2);
            Al[k]     = cvt2(p1 - h1, p0 - h0);
            Al[k + 2] = cvt2(p3 - h3, p2 - h2);
        }

        // ---- prefetch next chunk's adj ----
        if (ch + 1 < NCH) {
#pragma unroll
            for (int k = 0; k < 2; ++k) {
                alo[k] = *(const int2*)(rb[k] + (ch + 1) * 16);
                ahi[k] = *(const int2*)(rb[k] + (ch + 1) * 16 + 8);
            }
        }

        // ---- products ----
#pragma unroll
        for (int nt = 0; nt < 8; ++nt) mma16816(acc[nt], Ah, B4[nt].x, B4[nt].y);
#pragma unroll
        for (int nt = 0; nt < 8; ++nt) mma16816(acc[nt], Al, B4[nt].x, B4[nt].y);
#pragma unroll
        for (int nt = 0; nt < 8; ++nt) mma16816(acc[nt], Ah, B4[nt].z, B4[nt].w);
    }

    // ---- denominators: quad-reduce per row ----
#pragma unroll
    for (int k = 0; k < 2; ++k) {
        den2[k] += __shfl_xor_sync(0xffffffffu, den2[k], 1);
        den2[k] += __shfl_xor_sync(0xffffffffu, den2[k], 2);
    }
    if ((l & 3) == 0) {
        g_pden[split][i0 + w * 16 + rq]     = den2[0];
        g_pden[split][i0 + w * 16 + 8 + rq] = den2[1];
    }

    // ---- write fp32 partial numerators ----
    {
        const int row = i0 + w * 16 + rq;
#pragma unroll
        for (int n = 0; n < 8; ++n) {
            *(float2*)&g_pacc[split][row][n * 8 + cq]     = make_float2(acc[n][0], acc[n][1]);
            *(float2*)&g_pacc[split][row + 8][n * 8 + cq] = make_float2(acc[n][2], acc[n][3]);
        }
    }
}

// ---------------------------------------------------------------------------
// Kernel 3: combine splits, normalize, ELU.
// ---------------------------------------------------------------------------
__global__ void __launch_bounds__(256) combine_kernel(float* __restrict__ out) {
    const int idx = blockIdx.x * 256 + threadIdx.x;   // over 8192*64
    const int i = idx >> 6;
    const int c = idx & 63;
    float acc = 0.f, den = 0.f;
#pragma unroll
    for (int sp = 0; sp < JSPLITS; ++sp) {
        acc += g_pacc[sp][i][c];
        den += g_pden[sp][i];
    }
    if (den == 0.f) den = 1.f;
    float v = acc / den;
    out[idx] = v > 0.f ? v : expm1f(v);
}

// ---------------------------------------------------------------------------
extern "C" void kernel_launch(void* const* d_in, const int* in_sizes, int n_in,
                              void* d_out, int out_size) {
    const float* h   = (const float*)d_in[0];
    const float* W   = (const float*)d_in[1];
    const float* a   = (const float*)d_in[2];
    const int*   adj = (const int*)d_in[3];
    float* out = (float*)d_out;

    prep_w<<<32, 256>>>(W);
    wh_mma<<<128, 128>>>(h, a);
    attn_kernel<<<(NN / 128) * JSPLITS, 256>>>(adj);
    combine_kernel<<<NN * NOUT / 256, 256>>>(out);
}